// round 8
// baseline (speedup 1.0000x reference)
#include <cuda_runtime.h>
#include <cuda_fp16.h>
#include <cstdint>

#define N_NODES 100000
#define DEG 16
#define D 128
#define TILE_M 128
#define NTHREADS 256
#define STRH 136            // half pitch = 17 x 16B: LDSM conflict-free, 16B aligned

// fp16 scratch (Y1 incl. bias, Z)
__device__ __align__(16) __half g_Y1h[(size_t)N_NODES * D];
__device__ __align__(16) __half g_Zh [(size_t)N_NODES * D];

// smem: A[128][136]h, B[256][136]h (W1 rows 0-127 / W2 rows 128-255), bias[128]f
#define SMEM_A    0
#define SMEM_B    (TILE_M * STRH * 2)               // 34816
#define SMEM_BIAS (SMEM_B + 2 * D * STRH * 2)       // 104448
#define SMEM_TOTAL (SMEM_BIAS + D * 4)              // 104960

__device__ __forceinline__ uint32_t smem_u32(const void* p) {
    uint32_t a;
    asm("{ .reg .u64 t; cvta.to.shared.u64 t, %1; cvt.u32.u64 %0, t; }" : "=r"(a) : "l"(p));
    return a;
}

__device__ __forceinline__ void ldsm_x4(uint32_t& r0, uint32_t& r1, uint32_t& r2, uint32_t& r3,
                                        uint32_t addr) {
    asm volatile("ldmatrix.sync.aligned.m8n8.x4.shared.b16 {%0,%1,%2,%3}, [%4];"
                 : "=r"(r0), "=r"(r1), "=r"(r2), "=r"(r3) : "r"(addr));
}

__device__ __forceinline__ void mma_f16(float c[4], const uint32_t a[4], const uint32_t b[2]) {
    asm volatile(
        "mma.sync.aligned.m16n8k16.row.col.f32.f16.f16.f32 "
        "{%0,%1,%2,%3},{%4,%5,%6,%7},{%8,%9},{%0,%1,%2,%3};\n"
        : "+f"(c[0]), "+f"(c[1]), "+f"(c[2]), "+f"(c[3])
        : "r"(a[0]), "r"(a[1]), "r"(a[2]), "r"(a[3]),
          "r"(b[0]), "r"(b[1]));
}

extern __shared__ char smem_raw[];

// ---------------------------------------------------------------------------
// Kernel 1: fused fp16 GEMM (r6 epilogue, in-kernel W convert).
//   pass 0: Y1h = half(X@W1^T + (b1+b2));  pass 1: Zh = half(X@W2^T)
// ---------------------------------------------------------------------------
__global__ void __launch_bounds__(NTHREADS, 2)
gconv_gemm_h(const float* __restrict__ x,
             const float* __restrict__ W1, const float* __restrict__ b1,
             const float* __restrict__ W2, const float* __restrict__ b2)
{
    const uint32_t sb = smem_u32(smem_raw);
    float* bias_s = reinterpret_cast<float*>(smem_raw + SMEM_BIAS);

    const int tid  = threadIdx.x;
    const int warp = tid >> 5;
    const int lane = tid & 31;
    const int m0   = blockIdx.x * TILE_M;

    if (tid < D) bias_s[tid] = __ldg(b1 + tid) + __ldg(b2 + tid);

    // Stage B = [W1; W2] fp32 -> fp16 smem. 8192 float4 / 256 thr = 32 it.
    #pragma unroll
    for (int it = 0; it < 32; it++) {
        const int i   = it * NTHREADS + tid;
        const int row = i >> 5;                  // 0..255
        const int c4  = (i & 31) * 4;
        const float* src = (row < D) ? (W1 + (size_t)row * D + c4)
                                     : (W2 + (size_t)(row - D) * D + c4);
        float4 v = __ldg(reinterpret_cast<const float4*>(src));
        __half2 h0 = __floats2half2_rn(v.x, v.y);
        __half2 h1 = __floats2half2_rn(v.z, v.w);
        uint2 u;
        u.x = *reinterpret_cast<const unsigned*>(&h0);
        u.y = *reinterpret_cast<const unsigned*>(&h1);
        *reinterpret_cast<uint2*>(smem_raw + SMEM_B + (row * STRH + c4) * 2) = u;
    }
    // Stage A = x tile fp32 -> fp16 smem. 4096 float4 / 256 thr = 16 it.
    #pragma unroll
    for (int it = 0; it < 16; it++) {
        const int i   = it * NTHREADS + tid;
        const int row = i >> 5;                  // 0..127
        const int c4  = (i & 31) * 4;
        const int node = m0 + row;
        float4 v = make_float4(0.f, 0.f, 0.f, 0.f);
        if (node < N_NODES)
            v = __ldg(reinterpret_cast<const float4*>(x + (size_t)node * D + c4));
        __half2 h0 = __floats2half2_rn(v.x, v.y);
        __half2 h1 = __floats2half2_rn(v.z, v.w);
        uint2 u;
        u.x = *reinterpret_cast<const unsigned*>(&h0);
        u.y = *reinterpret_cast<const unsigned*>(&h1);
        *reinterpret_cast<uint2*>(smem_raw + SMEM_A + (row * STRH + c4) * 2) = u;
    }
    __syncthreads();

    const int wm = warp >> 2;   // 0..1 -> 64 rows
    const int wn = warp & 3;    // 0..3 -> 32 cols
    const int g  = lane >> 2;
    const int t  = lane & 3;

    const int arow = wm * 64 + (lane & 7) + ((lane >> 3) & 1) * 8;
    const int acol = ((lane >> 4) & 1) * 8;
    const uint32_t aBase = sb + SMEM_A + (arow * STRH + acol) * 2;
    const int brow = wn * 32 + (lane & 7) + ((lane >> 4) & 1) * 8;
    const int bcol = ((lane >> 3) & 1) * 8;
    const uint32_t bBase0 = sb + SMEM_B + (brow * STRH + bcol) * 2;

    #pragma unroll
    for (int pass = 0; pass < 2; pass++) {
        const uint32_t bBase = bBase0 + (uint32_t)pass * (D * STRH * 2);

        float c[4][4][4];
        #pragma unroll
        for (int mi = 0; mi < 4; mi++)
            #pragma unroll
            for (int ni = 0; ni < 4; ni++)
                #pragma unroll
                for (int r = 0; r < 4; r++) c[mi][ni][r] = 0.f;

        #pragma unroll
        for (int ks = 0; ks < 8; ks++) {
            const uint32_t koff = ks * 32;
            uint32_t a[4][4];
            #pragma unroll
            for (int mi = 0; mi < 4; mi++)
                ldsm_x4(a[mi][0], a[mi][1], a[mi][2], a[mi][3],
                        aBase + mi * (16 * STRH * 2) + koff);
            uint32_t b[4][2];
            #pragma unroll
            for (int p = 0; p < 2; p++) {
                uint32_t r0, r1, r2, r3;
                ldsm_x4(r0, r1, r2, r3, bBase + p * (16 * STRH * 2) + koff);
                b[p * 2 + 0][0] = r0; b[p * 2 + 0][1] = r1;
                b[p * 2 + 1][0] = r2; b[p * 2 + 1][1] = r3;
            }
            #pragma unroll
            for (int mi = 0; mi < 4; mi++)
                #pragma unroll
                for (int ni = 0; ni < 4; ni++)
                    mma_f16(c[mi][ni], a[mi], b[ni]);
        }

        __half* dst = (pass == 0) ? g_Y1h : g_Zh;
        const bool addBias = (pass == 0);
        #pragma unroll
        for (int mi = 0; mi < 4; mi++) {
            const int node0 = m0 + wm * 64 + mi * 16 + g;
            const int node1 = node0 + 8;
            #pragma unroll
            for (int ni = 0; ni < 4; ni++) {
                const int col = wn * 32 + ni * 8 + 2 * t;
                const float bs0 = addBias ? bias_s[col] : 0.f;
                const float bs1 = addBias ? bias_s[col + 1] : 0.f;
                if (node0 < N_NODES) {
                    __half2 h = __floats2half2_rn(c[mi][ni][0] + bs0, c[mi][ni][1] + bs1);
                    *reinterpret_cast<__half2*>(&dst[(size_t)node0 * D + col]) = h;
                }
                if (node1 < N_NODES) {
                    __half2 h = __floats2half2_rn(c[mi][ni][2] + bs0, c[mi][ni][3] + bs1);
                    *reinterpret_cast<__half2*>(&dst[(size_t)node1 * D + col]) = h;
                }
            }
        }
    }
}

// ---------------------------------------------------------------------------
// Kernel 2: gather.  out[n] = relu(Y1h[n] + sum_j Zh[nbr[n][j]])
// One warp/node. Pairwise fp16 add (HADD2) halves cvt+add instruction count;
// pair sums accumulated in fp32 (single accumulator set, low regs).
// ---------------------------------------------------------------------------
__global__ void __launch_bounds__(NTHREADS)
gconv_gather_kernel(const int* __restrict__ nbr,
                    float* __restrict__ out)
{
    const int warp = threadIdx.x >> 5;
    const int lane = threadIdx.x & 31;
    const int node = blockIdx.x * (NTHREADS / 32) + warp;
    if (node >= N_NODES) return;

    int idx = 0;
    if (lane < DEG) idx = __ldg(nbr + (size_t)node * DEG + lane);

    const uint2* Y2 = reinterpret_cast<const uint2*>(g_Y1h);
    const uint2* Z2 = reinterpret_cast<const uint2*>(g_Zh);

    uint2 yv = __ldg(Y2 + (size_t)node * 32 + lane);
    float2 a0 = __half22float2(*reinterpret_cast<const __half2*>(&yv.x));
    float2 a1 = __half22float2(*reinterpret_cast<const __half2*>(&yv.y));
    float4 acc = make_float4(a0.x, a0.y, a1.x, a1.y);

    #pragma unroll
    for (int j = 0; j < DEG; j += 2) {
        const int njA = __shfl_sync(0xffffffffu, idx, j);
        const int njB = __shfl_sync(0xffffffffu, idx, j + 1);
        uint2 zA = __ldg(Z2 + (size_t)njA * 32 + lane);
        uint2 zB = __ldg(Z2 + (size_t)njB * 32 + lane);
        // one-level pairwise fp16 add (safe: +~3e-4 rel in quadrature)
        __half2 p0 = __hadd2(*reinterpret_cast<const __half2*>(&zA.x),
                             *reinterpret_cast<const __half2*>(&zB.x));
        __half2 p1 = __hadd2(*reinterpret_cast<const __half2*>(&zA.y),
                             *reinterpret_cast<const __half2*>(&zB.y));
        float2 f0 = __half22float2(p0);
        float2 f1 = __half22float2(p1);
        acc.x += f0.x; acc.y += f0.y; acc.z += f1.x; acc.w += f1.y;
    }
    float4 r;
    r.x = fmaxf(acc.x, 0.f);
    r.y = fmaxf(acc.y, 0.f);
    r.z = fmaxf(acc.z, 0.f);
    r.w = fmaxf(acc.w, 0.f);
    *reinterpret_cast<float4*>(&out[(size_t)node * D + 4 * lane]) = r;
}

extern "C" void kernel_launch(void* const* d_in, const int* in_sizes, int n_in,
                              void* d_out, int out_size)
{
    const int*   nbr = (const int*)d_in[0];
    const float* x   = (const float*)d_in[1];
    const float* W1  = (const float*)d_in[2];
    const float* b1  = (const float*)d_in[3];
    const float* W2  = (const float*)d_in[4];
    const float* b2  = (const float*)d_in[5];
    float*       out = (float*)d_out;

    cudaFuncSetAttribute(gconv_gemm_h,
                         cudaFuncAttributeMaxDynamicSharedMemorySize, SMEM_TOTAL);

    const int grid1 = (N_NODES + TILE_M - 1) / TILE_M;   // 782
    gconv_gemm_h<<<grid1, NTHREADS, SMEM_TOTAL>>>(x, W1, b1, W2, b2);

    const int grid2 = (N_NODES + (NTHREADS / 32) - 1) / (NTHREADS / 32); // 12500
    gconv_gather_kernel<<<grid2, NTHREADS>>>(nbr, out);
}

// round 9
// speedup vs baseline: 1.0895x; 1.0895x over previous
#include <cuda_runtime.h>
#include <cuda_fp16.h>
#include <cstdint>

#define N_NODES 100000
#define DEG 16
#define D 128
#define TILE_M 256
#define NT_GEMM 512
#define NT_GATH 256
#define STRH 136            // half pitch = 17 x 16B: LDSM conflict-free, 16B aligned

// fp16 scratch (Y1 incl. bias, Z)
__device__ __align__(16) __half g_Y1h[(size_t)N_NODES * D];
__device__ __align__(16) __half g_Zh [(size_t)N_NODES * D];

// smem: A[256][136]h, B[256][136]h (W1 rows 0-127 / W2 rows 128-255), bias[128]f
#define SMEM_A    0
#define SMEM_B    (TILE_M * STRH * 2)               // 69632
#define SMEM_BIAS (SMEM_B + 2 * D * STRH * 2)       // 139264
#define SMEM_TOTAL (SMEM_BIAS + D * 4)              // 139776

__device__ __forceinline__ uint32_t smem_u32(const void* p) {
    uint32_t a;
    asm("{ .reg .u64 t; cvta.to.shared.u64 t, %1; cvt.u32.u64 %0, t; }" : "=r"(a) : "l"(p));
    return a;
}

__device__ __forceinline__ void ldsm_x4(uint32_t& r0, uint32_t& r1, uint32_t& r2, uint32_t& r3,
                                        uint32_t addr) {
    asm volatile("ldmatrix.sync.aligned.m8n8.x4.shared.b16 {%0,%1,%2,%3}, [%4];"
                 : "=r"(r0), "=r"(r1), "=r"(r2), "=r"(r3) : "r"(addr));
}

__device__ __forceinline__ void mma_f16(float c[4], const uint32_t a[4], const uint32_t b[2]) {
    asm volatile(
        "mma.sync.aligned.m16n8k16.row.col.f32.f16.f16.f32 "
        "{%0,%1,%2,%3},{%4,%5,%6,%7},{%8,%9},{%0,%1,%2,%3};\n"
        : "+f"(c[0]), "+f"(c[1]), "+f"(c[2]), "+f"(c[3])
        : "r"(a[0]), "r"(a[1]), "r"(a[2]), "r"(a[3]),
          "r"(b[0]), "r"(b[1]));
}

extern __shared__ char smem_raw[];

// ---------------------------------------------------------------------------
// Kernel 1: fused fp16 GEMM, TILE_M=256, 512 threads (16 warps).
//   pass 0: Y1h = half(X@W1^T + (b1+b2));  pass 1: Zh = half(X@W2^T)
// W staged fp32->fp16 in-kernel; halved CTA count halves W L2 traffic.
// ---------------------------------------------------------------------------
__global__ void __launch_bounds__(NT_GEMM, 1)
gconv_gemm_h(const float* __restrict__ x,
             const float* __restrict__ W1, const float* __restrict__ b1,
             const float* __restrict__ W2, const float* __restrict__ b2)
{
    const uint32_t sb = smem_u32(smem_raw);
    float* bias_s = reinterpret_cast<float*>(smem_raw + SMEM_BIAS);

    const int tid  = threadIdx.x;
    const int warp = tid >> 5;
    const int lane = tid & 31;
    const int m0   = blockIdx.x * TILE_M;

    if (tid < D) bias_s[tid] = __ldg(b1 + tid) + __ldg(b2 + tid);

    // Stage B = [W1; W2] fp32 -> fp16 smem. 8192 float4 / 512 thr = 16 it.
    #pragma unroll
    for (int it = 0; it < 16; it++) {
        const int i   = it * NT_GEMM + tid;
        const int row = i >> 5;                  // 0..255
        const int c4  = (i & 31) * 4;
        const float* src = (row < D) ? (W1 + (size_t)row * D + c4)
                                     : (W2 + (size_t)(row - D) * D + c4);
        float4 v = __ldg(reinterpret_cast<const float4*>(src));
        __half2 h0 = __floats2half2_rn(v.x, v.y);
        __half2 h1 = __floats2half2_rn(v.z, v.w);
        uint2 u;
        u.x = *reinterpret_cast<const unsigned*>(&h0);
        u.y = *reinterpret_cast<const unsigned*>(&h1);
        *reinterpret_cast<uint2*>(smem_raw + SMEM_B + (row * STRH + c4) * 2) = u;
    }
    // Stage A = x tile (256x128) fp32 -> fp16 smem. 8192 float4 / 512 thr = 16 it.
    #pragma unroll
    for (int it = 0; it < 16; it++) {
        const int i   = it * NT_GEMM + tid;
        const int row = i >> 5;                  // 0..255
        const int c4  = (i & 31) * 4;
        const int node = m0 + row;
        float4 v = make_float4(0.f, 0.f, 0.f, 0.f);
        if (node < N_NODES)
            v = __ldg(reinterpret_cast<const float4*>(x + (size_t)node * D + c4));
        __half2 h0 = __floats2half2_rn(v.x, v.y);
        __half2 h1 = __floats2half2_rn(v.z, v.w);
        uint2 u;
        u.x = *reinterpret_cast<const unsigned*>(&h0);
        u.y = *reinterpret_cast<const unsigned*>(&h1);
        *reinterpret_cast<uint2*>(smem_raw + SMEM_A + (row * STRH + c4) * 2) = u;
    }
    __syncthreads();

    const int wm = warp >> 2;   // 0..3 -> 64 rows each (256 total)
    const int wn = warp & 3;    // 0..3 -> 32 cols each
    const int g  = lane >> 2;
    const int t  = lane & 3;

    const int arow = wm * 64 + (lane & 7) + ((lane >> 3) & 1) * 8;
    const int acol = ((lane >> 4) & 1) * 8;
    const uint32_t aBase = sb + SMEM_A + (arow * STRH + acol) * 2;
    const int brow = wn * 32 + (lane & 7) + ((lane >> 4) & 1) * 8;
    const int bcol = ((lane >> 3) & 1) * 8;
    const uint32_t bBase0 = sb + SMEM_B + (brow * STRH + bcol) * 2;

    #pragma unroll
    for (int pass = 0; pass < 2; pass++) {
        const uint32_t bBase = bBase0 + (uint32_t)pass * (D * STRH * 2);

        float c[4][4][4];
        #pragma unroll
        for (int mi = 0; mi < 4; mi++)
            #pragma unroll
            for (int ni = 0; ni < 4; ni++)
                #pragma unroll
                for (int r = 0; r < 4; r++) c[mi][ni][r] = 0.f;

        #pragma unroll
        for (int ks = 0; ks < 8; ks++) {
            const uint32_t koff = ks * 32;
            uint32_t a[4][4];
            #pragma unroll
            for (int mi = 0; mi < 4; mi++)
                ldsm_x4(a[mi][0], a[mi][1], a[mi][2], a[mi][3],
                        aBase + mi * (16 * STRH * 2) + koff);
            uint32_t b[4][2];
            #pragma unroll
            for (int p = 0; p < 2; p++) {
                uint32_t r0, r1, r2, r3;
                ldsm_x4(r0, r1, r2, r3, bBase + p * (16 * STRH * 2) + koff);
                b[p * 2 + 0][0] = r0; b[p * 2 + 0][1] = r1;
                b[p * 2 + 1][0] = r2; b[p * 2 + 1][1] = r3;
            }
            #pragma unroll
            for (int mi = 0; mi < 4; mi++)
                #pragma unroll
                for (int ni = 0; ni < 4; ni++)
                    mma_f16(c[mi][ni], a[mi], b[ni]);
        }

        __half* dst = (pass == 0) ? g_Y1h : g_Zh;
        const bool addBias = (pass == 0);
        #pragma unroll
        for (int mi = 0; mi < 4; mi++) {
            const int node0 = m0 + wm * 64 + mi * 16 + g;
            const int node1 = node0 + 8;
            #pragma unroll
            for (int ni = 0; ni < 4; ni++) {
                const int col = wn * 32 + ni * 8 + 2 * t;
                const float bs0 = addBias ? bias_s[col] : 0.f;
                const float bs1 = addBias ? bias_s[col + 1] : 0.f;
                if (node0 < N_NODES) {
                    __half2 h = __floats2half2_rn(c[mi][ni][0] + bs0, c[mi][ni][1] + bs1);
                    *reinterpret_cast<__half2*>(&dst[(size_t)node0 * D + col]) = h;
                }
                if (node1 < N_NODES) {
                    __half2 h = __floats2half2_rn(c[mi][ni][2] + bs0, c[mi][ni][3] + bs1);
                    *reinterpret_cast<__half2*>(&dst[(size_t)node1 * D + col]) = h;
                }
            }
        }
    }
}

// ---------------------------------------------------------------------------
// Kernel 2: gather (r8 best).  out[n] = relu(Y1h[n] + sum_j Zh[nbr[n][j]])
// One warp/node; pairwise HADD2 then fp32 accumulate.
// ---------------------------------------------------------------------------
__global__ void __launch_bounds__(NT_GATH)
gconv_gather_kernel(const int* __restrict__ nbr,
                    float* __restrict__ out)
{
    const int warp = threadIdx.x >> 5;
    const int lane = threadIdx.x & 31;
    const int node = blockIdx.x * (NT_GATH / 32) + warp;
    if (node >= N_NODES) return;

    int idx = 0;
    if (lane < DEG) idx = __ldg(nbr + (size_t)node * DEG + lane);

    const uint2* Y2 = reinterpret_cast<const uint2*>(g_Y1h);
    const uint2* Z2 = reinterpret_cast<const uint2*>(g_Zh);

    uint2 yv = __ldg(Y2 + (size_t)node * 32 + lane);
    float2 a0 = __half22float2(*reinterpret_cast<const __half2*>(&yv.x));
    float2 a1 = __half22float2(*reinterpret_cast<const __half2*>(&yv.y));
    float4 acc = make_float4(a0.x, a0.y, a1.x, a1.y);

    #pragma unroll
    for (int j = 0; j < DEG; j += 2) {
        const int njA = __shfl_sync(0xffffffffu, idx, j);
        const int njB = __shfl_sync(0xffffffffu, idx, j + 1);
        uint2 zA = __ldg(Z2 + (size_t)njA * 32 + lane);
        uint2 zB = __ldg(Z2 + (size_t)njB * 32 + lane);
        __half2 p0 = __hadd2(*reinterpret_cast<const __half2*>(&zA.x),
                             *reinterpret_cast<const __half2*>(&zB.x));
        __half2 p1 = __hadd2(*reinterpret_cast<const __half2*>(&zA.y),
                             *reinterpret_cast<const __half2*>(&zB.y));
        float2 f0 = __half22float2(p0);
        float2 f1 = __half22float2(p1);
        acc.x += f0.x; acc.y += f0.y; acc.z += f1.x; acc.w += f1.y;
    }
    float4 r;
    r.x = fmaxf(acc.x, 0.f);
    r.y = fmaxf(acc.y, 0.f);
    r.z = fmaxf(acc.z, 0.f);
    r.w = fmaxf(acc.w, 0.f);
    *reinterpret_cast<float4*>(&out[(size_t)node * D + 4 * lane]) = r;
}

extern "C" void kernel_launch(void* const* d_in, const int* in_sizes, int n_in,
                              void* d_out, int out_size)
{
    const int*   nbr = (const int*)d_in[0];
    const float* x   = (const float*)d_in[1];
    const float* W1  = (const float*)d_in[2];
    const float* b1  = (const float*)d_in[3];
    const float* W2  = (const float*)d_in[4];
    const float* b2  = (const float*)d_in[5];
    float*       out = (float*)d_out;

    cudaFuncSetAttribute(gconv_gemm_h,
                         cudaFuncAttributeMaxDynamicSharedMemorySize, SMEM_TOTAL);

    const int grid1 = (N_NODES + TILE_M - 1) / TILE_M;   // 391
    gconv_gemm_h<<<grid1, NT_GEMM, SMEM_TOTAL>>>(x, W1, b1, W2, b2);

    const int grid2 = (N_NODES + (NT_GATH / 32) - 1) / (NT_GATH / 32); // 12500
    gconv_gather_kernel<<<grid2, NT_GATH>>>(nbr, out);
}